// round 6
// baseline (speedup 1.0000x reference)
#include <cuda_runtime.h>
#include <cstdint>

#define BGRAPHS   16
#define NPG       2048
#define KNN       16
#define MIN_DISTR 5
#define CPB       32                 // centers per block
#define PARTS     8                  // threads per center
#define PAIRS_PT  (NPG / 2 / PARTS)  // 128 candidate-pairs per thread
#define THREADS   (CPB * PARTS)      // 256 threads per block
#define CAP       160                // pass-2 collection capacity per center

// ---- packed f32x2 helpers (Blackwell sm_10x) ----
#define MUL2(d, a, b)     asm("mul.rn.f32x2 %0, %1, %2;"     : "=l"(d) : "l"(a), "l"(b))
#define ADD2(d, a, b)     asm("add.rn.f32x2 %0, %1, %2;"     : "=l"(d) : "l"(a), "l"(b))
#define FMA2(d, a, b, c)  asm("fma.rn.f32x2 %0, %1, %2, %3;" : "=l"(d) : "l"(a), "l"(b), "l"(c))
#define PACK2(d, lo, hi)  asm("mov.b64 %0, {%1, %2};"        : "=l"(d) : "f"(lo), "f"(hi))
#define UNPK2(lo, hi, s)  asm("mov.b64 {%0, %1}, %2;"        : "=f"(lo), "=f"(hi) : "l"(s))

// monotone float -> uint key (total order matching float <)
__device__ __forceinline__ unsigned sortkey(float f)
{
    unsigned u = __float_as_uint(f);
    return u ^ (unsigned)(((int)u >> 31) | 0x80000000);
}

// exact reference-rounded d^2 (scalar) — must match the packed path bit-for-bit
__device__ __forceinline__ float d2_scalar(float cx, float cy, float cz, float csq,
                                           float x, float y, float z, float w)
{
    float dot = __fmaf_rn(cz, z, __fmaf_rn(cy, y, __fmul_rn(cx, x)));
    return __fmaf_rn(-2.0f, dot, __fadd_rn(csq, w));
}

__global__ __launch_bounds__(THREADS, 5)
void knn_kernel(const float* __restrict__ pos, float2* __restrict__ out)
{
    // SoA-pair layout: shA[t] = {x(2t),x(2t+1),y(2t),y(2t+1)}
    //                  shB[t] = {z(2t),z(2t+1),w(2t),w(2t+1)}  (w = |p|^2)
    __shared__ ulonglong2     shA[NPG / 2];          // 16 KB
    __shared__ ulonglong2     shB[NPG / 2];          // 16 KB
    __shared__ float          h1s[CPB * PARTS * 2];  //  2 KB (2nd-smallest per half-substream)
    __shared__ float          bnd[CPB];
    __shared__ int            cnt[CPB];
    __shared__ unsigned short jbuf[CPB * CAP];       // 10 KB

    const int tid = threadIdx.x;
    const int p   = tid >> 5;        // part 0..7 (uniform per warp)
    const int c   = tid & 31;        // center-in-block (lane)

    const int g  = blockIdx.x >> 6;           // 64 blocks per graph
    const int cb = (blockIdx.x & 63) * CPB;   // center base (local)
    const int gb = g * NPG;

    if (tid < CPB) cnt[tid] = 0;

    // ---- load graph into packed smem; sq per reference rounding ----
    for (int t = tid; t < NPG / 2; t += THREADS) {
        const float* q = pos + 3ull * (unsigned long long)(gb + 2 * t);
        float x0 = q[0], y0 = q[1], z0 = q[2];
        float x1 = q[3], y1 = q[4], z1 = q[5];
        float w0 = __fadd_rn(__fadd_rn(__fmul_rn(x0, x0), __fmul_rn(y0, y0)),
                             __fmul_rn(z0, z0));
        float w1 = __fadd_rn(__fadd_rn(__fmul_rn(x1, x1), __fmul_rn(y1, y1)),
                             __fmul_rn(z1, z1));
        unsigned long long ax, ay, bz, bw;
        PACK2(ax, x0, x1); PACK2(ay, y0, y1);
        PACK2(bz, z0, z1); PACK2(bw, w0, w1);
        shA[t] = make_ulonglong2(ax, ay);
        shB[t] = make_ulonglong2(bz, bw);
    }
    __syncthreads();

    // center coords (scalar, from packed layout)
    const int lc = cb + c;
    float cx, cy, cz, csq;
    {
        const float* fA = (const float*)&shA[lc >> 1];
        const float* fB = (const float*)&shB[lc >> 1];
        const int h = lc & 1;
        cx = fA[h]; cy = fA[2 + h]; cz = fB[h]; csq = fB[2 + h];
    }
    unsigned long long cx2, cy2, cz2, cs2, n22;
    PACK2(cx2, cx, cx); PACK2(cy2, cy, cy); PACK2(cz2, cz, cz);
    PACK2(cs2, csq, csq);
    PACK2(n22, -2.0f, -2.0f);

    const float INF = __int_as_float(0x7f800000);

    // ---- pass 1: per half-substream 2-smallest values (self flows through) ----
    float a0 = INF, a1 = INF;    // even-candidate half
    float b0 = INF, b1 = INF;    // odd-candidate half
    const int tb = p * PAIRS_PT;
#pragma unroll 4
    for (int t = tb; t < tb + PAIRS_PT; ++t) {
        const ulonglong2 A = shA[t];
        const ulonglong2 B = shB[t];
        unsigned long long pd, ps, pd2;
        MUL2(pd, A.x, cx2);
        FMA2(pd, A.y, cy2, pd);
        FMA2(pd, B.x, cz2, pd);
        ADD2(ps, B.y, cs2);
        FMA2(pd2, pd, n22, ps);
        float da, db;
        UNPK2(da, db, pd2);
        // 2-smallest chains, 3 FMNMX each
        float t0 = fminf(a0, da); float xa = fmaxf(a0, da); a0 = t0; a1 = fminf(a1, xa);
        float t1 = fminf(b0, db); float xb = fmaxf(b0, db); b0 = t1; b1 = fminf(b1, xb);
    }
    h1s[(c * PARTS + p) * 2 + 0] = a1;
    h1s[(c * PARTS + p) * 2 + 1] = b1;
    __syncthreads();

    // ---- bound: max of the 16 2nd-smallest values ----
    // validity: each half-substream has >=2 elements <= its h1 <= B => >=32
    // distinct elements <= B, >=31 excluding self => B >= true 16th smallest.
    if (tid < CPB) {
        const float* H = h1s + tid * PARTS * 2;
        float B = H[0];
#pragma unroll
        for (int e = 1; e < PARTS * 2; ++e) B = fmaxf(B, H[e]);
        bnd[tid] = B;
    }
    __syncthreads();

    // ---- pass 2: collect candidate indices with d2 <= B ----
    const float B = bnd[c];
#pragma unroll 4
    for (int t = tb; t < tb + PAIRS_PT; ++t) {
        const ulonglong2 A = shA[t];
        const ulonglong2 Bv = shB[t];
        unsigned long long pd, ps, pd2;
        MUL2(pd, A.x, cx2);
        FMA2(pd, A.y, cy2, pd);
        FMA2(pd, Bv.x, cz2, pd);
        ADD2(ps, Bv.y, cs2);
        FMA2(pd2, pd, n22, ps);
        float da, db;
        UNPK2(da, db, pd2);
        if ((da <= B) || (db <= B)) {
            const int j0 = 2 * t, j1 = 2 * t + 1;
            if (da <= B && j0 != lc) {
                int s = atomicAdd(&cnt[c], 1);
                if (s < CAP) jbuf[c * CAP + s] = (unsigned short)j0;
            }
            if (db <= B && j1 != lc) {
                int s = atomicAdd(&cnt[c], 1);
                if (s < CAP) jbuf[c * CAP + s] = (unsigned short)j1;
            }
        }
    }
    __syncthreads();

    // ---- selection + filters + emit: one lane per center ----
    if (tid < CPB) {
        const int c2  = tid;
        const int lc2 = cb + c2;
        const float* fA0 = (const float*)&shA[lc2 >> 1];
        const float* fB0 = (const float*)&shB[lc2 >> 1];
        const int h0 = lc2 & 1;
        const float ax = fA0[h0], ay = fA0[2 + h0], az = fB0[h0], asq = fB0[2 + h0];

        unsigned long long hd[KNN];
#pragma unroll
        for (int t = 0; t < KNN; ++t) hd[t] = ~0ull;

        const int m = cnt[c2];
        if (m <= CAP) {
            for (int e = 0; e < m; ++e) {
                const int j = jbuf[c2 * CAP + e];
                const float* fA = (const float*)&shA[j >> 1];
                const float* fB = (const float*)&shB[j >> 1];
                const int h = j & 1;
                float d2 = d2_scalar(ax, ay, az, asq, fA[h], fA[2 + h], fB[h], fB[2 + h]);
                unsigned long long key =
                    ((unsigned long long)sortkey(d2) << 32) | (unsigned)j;
                if (key < hd[KNN - 1]) {
#pragma unroll
                    for (int t = 0; t < KNN; ++t) {
                        unsigned long long lo = key < hd[t] ? key : hd[t];
                        unsigned long long hi = key < hd[t] ? hd[t] : key;
                        hd[t] = lo; key = hi;
                    }
                }
            }
        } else {
            // overflow fallback: exact full scan (deterministic)
            for (int j = 0; j < NPG; ++j) {
                if (j == lc2) continue;
                const float* fA = (const float*)&shA[j >> 1];
                const float* fB = (const float*)&shB[j >> 1];
                const int h = j & 1;
                float d2 = d2_scalar(ax, ay, az, asq, fA[h], fA[2 + h], fB[h], fB[2 + h]);
                unsigned long long key =
                    ((unsigned long long)sortkey(d2) << 32) | (unsigned)j;
                if (key < hd[KNN - 1]) {
#pragma unroll
                    for (int t = 0; t < KNN; ++t) {
                        unsigned long long lo = key < hd[t] ? key : hd[t];
                        unsigned long long hi = key < hd[t] ? hd[t] : key;
                        hd[t] = lo; key = hi;
                    }
                }
            }
        }

        const int ctr = gb + lc2;
#pragma unroll
        for (int k = 0; k < KNN; ++k) {
            float2 e = make_float2(-1.0f, -1.0f);
            if (hd[k] != ~0ull) {
                const int nl  = (int)(unsigned)(hd[k] & 0xFFFFFFFFull);
                const int nbr = gb + nl;
                const float* fA = (const float*)&shA[nl >> 1];
                const float* fB = (const float*)&shB[nl >> 1];
                const int h = nl & 1;
                // degenerate-edge filter, reference formula
                float dx = __fadd_rn(fA[h], -ax);
                float dy = __fadd_rn(fA[2 + h], -ay);
                float dz = __fadd_rn(fB[h], -az);
                float dn2 = __fadd_rn(__fadd_rn(__fmul_rn(dx, dx), __fmul_rn(dy, dy)),
                                      __fmul_rn(dz, dz));
                int  rd    = nbr > ctr ? (nbr - ctr) : (ctr - nbr);
                bool valid = (rd >= MIN_DISTR) && (sqrtf(dn2) >= 1e-10f);
                if (valid) e = make_float2((float)nbr, (float)ctr);
            }
            out[ctr * KNN + k] = e;
        }
    }
}

extern "C" void kernel_launch(void* const* d_in, const int* in_sizes, int n_in,
                              void* d_out, int out_size)
{
    const float* pos = (const float*)d_in[0];
    for (int i = 0; i < n_in; ++i)
        if (in_sizes[i] == BGRAPHS * NPG * 3) { pos = (const float*)d_in[i]; break; }
    float2* out = (float2*)d_out;

    dim3 grid(BGRAPHS * (NPG / CPB));   // 1024 blocks
    dim3 block(THREADS);                // 256 threads
    knn_kernel<<<grid, block>>>(pos, out);
}

// round 7
// speedup vs baseline: 2.6228x; 2.6228x over previous
#include <cuda_runtime.h>
#include <cstdint>

#define BGRAPHS   16
#define NPG       2048
#define KNN       16
#define MIN_DISTR 5
#define CPB       32                 // centers per tile
#define TILES     2                  // center-tiles per block (single-wave grid)
#define PARTS     8                  // threads per center
#define CANDS     (NPG / PARTS)      // 256 candidates per part
#define THREADS   (CPB * PARTS)      // 256 threads per block
#define CAP       128                // pass-2 collection capacity per center

// monotone float -> uint key (total order matching float <)
__device__ __forceinline__ unsigned sortkey(float f)
{
    unsigned u = __float_as_uint(f);
    return u ^ (unsigned)(((int)u >> 31) | 0x80000000);
}

// exact reference-rounded squared distance (validated rounds 3-5)
__device__ __forceinline__ float d2_ref(float cx, float cy, float cz, float csq,
                                        const float4 v)
{
    float dot = __fmaf_rn(cz, v.z, __fmaf_rn(cy, v.y, __fmul_rn(cx, v.x)));
    return __fmaf_rn(-2.0f, dot, __fadd_rn(csq, v.w));
}

__global__ __launch_bounds__(THREADS, 4)
void knn_kernel(const float* __restrict__ pos, float2* __restrict__ out)
{
    __shared__ float4         sh[NPG];             // 32 KB: x,y,z,|p|^2
    __shared__ float          h1s[CPB * PARTS];    //  1 KB: per-part 2nd-smallest
    __shared__ float          bnd[CPB];
    __shared__ int            cnt[CPB];
    __shared__ unsigned short jbuf[CPB * CAP];     //  8 KB

    const int tid = threadIdx.x;
    const int p   = tid >> 5;        // part 0..7 (uniform per warp)
    const int c   = tid & 31;        // center-in-tile (lane)

    const int g   = blockIdx.x >> 5;                        // 32 blocks per graph
    const int tb0 = (blockIdx.x & 31) * (CPB * TILES);      // first center of block
    const int gb  = g * NPG;

    // ---- load whole graph once per block; sq per reference rounding ----
    for (int i = tid; i < NPG; i += THREADS) {
        const float* q = pos + 3ull * (unsigned long long)(gb + i);
        float x = q[0], y = q[1], z = q[2];
        float sq = __fadd_rn(__fadd_rn(__fmul_rn(x, x), __fmul_rn(y, y)),
                             __fmul_rn(z, z));
        sh[i] = make_float4(x, y, z, sq);
    }
    __syncthreads();

    const float INF = __int_as_float(0x7f800000);
    const int   jb  = p * CANDS;

    for (int tile = 0; tile < TILES; ++tile) {
        const int cb = tb0 + tile * CPB;
        if (tid < CPB) cnt[tid] = 0;

        const int    lc = cb + c;
        const float4 cc = sh[lc];
        const float  cx = cc.x, cy = cc.y, cz = cc.z, csq = cc.w;

        // ---- pass 1: exact 2-smallest of this part's non-self candidates ----
        // batched min2-of-8 network: no loop-carried chain inside the batch
        float h0 = INF, h1 = INF;
        for (int j0 = jb; j0 < jb + CANDS; j0 += 8) {
            float d[8];
#pragma unroll
            for (int k = 0; k < 8; ++k) {
                float dd = d2_ref(cx, cy, cz, csq, sh[j0 + k]);
                d[k] = (j0 + k == lc) ? INF : dd;    // exclude self
            }
            // level 1: 4 sorted pairs
            float m0 = fminf(d[0], d[1]), M0 = fmaxf(d[0], d[1]);
            float m1 = fminf(d[2], d[3]), M1 = fmaxf(d[2], d[3]);
            float m2 = fminf(d[4], d[5]), M2 = fmaxf(d[4], d[5]);
            float m3 = fminf(d[6], d[7]), M3 = fmaxf(d[6], d[7]);
            // combine pairs: 2-smallest of union = (min(m,m'), min(max(m,m'), M, M'))
            float ma = fminf(m0, m1), ta = fmaxf(m0, m1);
            float sa = fminf(ta, fminf(M0, M1));
            float mb = fminf(m2, m3), tb = fmaxf(m2, m3);
            float sb = fminf(tb, fminf(M2, M3));
            float mc = fminf(ma, mb), tc = fmaxf(ma, mb);
            float sc = fminf(tc, fminf(sa, sb));
            // merge batch result into carried (h0, h1) — once per 8 candidates
            float t = fmaxf(h0, mc);
            h0 = fminf(h0, mc);
            h1 = fminf(fminf(t, h1), sc);
        }
        h1s[c * PARTS + p] = h1;
        __syncthreads();

        // ---- bound: max of the 8 per-part 2nd-smallest values ----
        // each part has >=2 valid (non-self) elements <= its h1 <= B
        // => >=16 valid elements <= B => B >= true 16th smallest
        if (tid < CPB) {
            const float* H = h1s + tid * PARTS;
            float B = H[0];
#pragma unroll
            for (int e = 1; e < PARTS; ++e) B = fmaxf(B, H[e]);
            bnd[tid] = B;
        }
        __syncthreads();

        // ---- pass 2: collect candidate indices with d2 <= B (self included) ----
        const float B = bnd[c];
#pragma unroll 4
        for (int j = jb; j < jb + CANDS; ++j) {
            float dd = d2_ref(cx, cy, cz, csq, sh[j]);
            if (dd <= B) {
                int s = atomicAdd(&cnt[c], 1);
                if (s < CAP) jbuf[c * CAP + s] = (unsigned short)j;
            }
        }
        __syncthreads();

        // ---- selection + filters + emit: one lane per center ----
        if (tid < CPB) {
            const int    lc2 = cb + tid;
            const float4 c0  = sh[lc2];
            const float  ax = c0.x, ay = c0.y, az = c0.z, asq = c0.w;

            unsigned long long hd[KNN];
#pragma unroll
            for (int t = 0; t < KNN; ++t) hd[t] = ~0ull;

            const int m = cnt[tid];
            if (m <= CAP) {
                for (int e = 0; e < m; ++e) {
                    const int j = jbuf[tid * CAP + e];
                    if (j == lc2) continue;          // skip self
                    float d2 = d2_ref(ax, ay, az, asq, sh[j]);
                    unsigned long long key =
                        ((unsigned long long)sortkey(d2) << 32) | (unsigned)j;
                    if (key < hd[KNN - 1]) {
#pragma unroll
                        for (int t = 0; t < KNN; ++t) {
                            unsigned long long lo = key < hd[t] ? key : hd[t];
                            unsigned long long hi = key < hd[t] ? hd[t] : key;
                            hd[t] = lo; key = hi;
                        }
                    }
                }
            } else {
                // overflow fallback: exact full scan (deterministic, ~never)
                for (int j = 0; j < NPG; ++j) {
                    if (j == lc2) continue;
                    float d2 = d2_ref(ax, ay, az, asq, sh[j]);
                    unsigned long long key =
                        ((unsigned long long)sortkey(d2) << 32) | (unsigned)j;
                    if (key < hd[KNN - 1]) {
#pragma unroll
                        for (int t = 0; t < KNN; ++t) {
                            unsigned long long lo = key < hd[t] ? key : hd[t];
                            unsigned long long hi = key < hd[t] ? hd[t] : key;
                            hd[t] = lo; key = hi;
                        }
                    }
                }
            }

            const int ctr = gb + lc2;
#pragma unroll
            for (int k = 0; k < KNN; ++k) {
                float2 e = make_float2(-1.0f, -1.0f);
                if (hd[k] != ~0ull) {
                    const int nl  = (int)(unsigned)(hd[k] & 0xFFFFFFFFull);
                    const int nbr = gb + nl;
                    const float4 v = sh[nl];
                    // degenerate-edge filter, reference formula
                    float dx = __fadd_rn(v.x, -ax);
                    float dy = __fadd_rn(v.y, -ay);
                    float dz = __fadd_rn(v.z, -az);
                    float dn2 = __fadd_rn(__fadd_rn(__fmul_rn(dx, dx),
                                                    __fmul_rn(dy, dy)),
                                          __fmul_rn(dz, dz));
                    int  rd    = nbr > ctr ? (nbr - ctr) : (ctr - nbr);
                    bool valid = (rd >= MIN_DISTR) && (sqrtf(dn2) >= 1e-10f);
                    if (valid) e = make_float2((float)nbr, (float)ctr);
                }
                out[ctr * KNN + k] = e;
            }
        }
        __syncthreads();   // protect cnt/jbuf/h1s before next tile reuses them
    }
}

extern "C" void kernel_launch(void* const* d_in, const int* in_sizes, int n_in,
                              void* d_out, int out_size)
{
    const float* pos = (const float*)d_in[0];
    for (int i = 0; i < n_in; ++i)
        if (in_sizes[i] == BGRAPHS * NPG * 3) { pos = (const float*)d_in[i]; break; }
    float2* out = (float2*)d_out;

    dim3 grid(BGRAPHS * (NPG / (CPB * TILES)));   // 512 blocks: single wave
    dim3 block(THREADS);                          // 256 threads
    knn_kernel<<<grid, block>>>(pos, out);
}

// round 8
// speedup vs baseline: 3.2082x; 1.2232x over previous
#include <cuda_runtime.h>
#include <cstdint>

#define BGRAPHS   16
#define NPG       2048
#define KNN       16
#define MIN_DISTR 5
#define CPB       64                 // centers per block
#define PARTS     4                  // threads per center
#define CANDS     (NPG / PARTS)      // 512 candidates per part
#define THREADS   (CPB * PARTS)      // 256 threads per block
#define CAP       128                // pass-2 collection capacity per center

// dynamic smem layout (bytes)
#define OFF_SH     0
#define OFF_PV     (OFF_SH + NPG * 16)            // 32768: per-part 4-smallest
#define OFF_BND    (OFF_PV + CPB * PARTS * 4 * 4) // +4096
#define OFF_CNT    (OFF_BND + CPB * 4)
#define OFF_JBUF   (OFF_CNT + CPB * 4)
#define SMEM_TOTAL (OFF_JBUF + CPB * CAP * 2)     // 53760 B

// monotone float -> uint key (total order matching float <)
__device__ __forceinline__ unsigned sortkey(float f)
{
    unsigned u = __float_as_uint(f);
    return u ^ (unsigned)(((int)u >> 31) | 0x80000000);
}

// exact reference-rounded squared distance (validated rounds 3-5)
__device__ __forceinline__ float d2_ref(float cx, float cy, float cz, float csq,
                                        const float4 v)
{
    float dot = __fmaf_rn(cz, v.z, __fmaf_rn(cy, v.y, __fmul_rn(cx, v.x)));
    return __fmaf_rn(-2.0f, dot, __fadd_rn(csq, v.w));
}

__global__ __launch_bounds__(THREADS, 4)
void knn_kernel(const float* __restrict__ pos, float2* __restrict__ out)
{
    extern __shared__ char dyns[];
    float4*         sh   = (float4*)(dyns + OFF_SH);
    float*          pv   = (float*)(dyns + OFF_PV);
    float*          bnd  = (float*)(dyns + OFF_BND);
    int*            cnt  = (int*)(dyns + OFF_CNT);
    unsigned short* jbuf = (unsigned short*)(dyns + OFF_JBUF);

    const int tid = threadIdx.x;
    const int p   = tid >> 6;        // part 0..3 (uniform per 2 warps)
    const int c   = tid & 63;        // center-in-block

    const int g  = blockIdx.x >> 5;           // 32 blocks per graph
    const int cb = (blockIdx.x & 31) * CPB;   // center base (local)
    const int gb = g * NPG;

    if (tid < CPB) cnt[tid] = 0;

    // ---- load whole graph; sq per reference rounding ----
    for (int i = tid; i < NPG; i += THREADS) {
        const float* q = pos + 3ull * (unsigned long long)(gb + i);
        float x = q[0], y = q[1], z = q[2];
        float sq = __fadd_rn(__fadd_rn(__fmul_rn(x, x), __fmul_rn(y, y)),
                             __fmul_rn(z, z));
        sh[i] = make_float4(x, y, z, sq);
    }
    __syncthreads();

    const int    lc = cb + c;
    const float4 cc = sh[lc];
    const float  cx = cc.x, cy = cc.y, cz = cc.z, csq = cc.w;
    const float  INF = __int_as_float(0x7f800000);

    // ---- pass 1: 4 smallest of this part's non-self substream (branchless) ----
    float h0 = INF, h1 = INF, h2 = INF, h3 = INF;
    const int jb = p * CANDS;
#pragma unroll 8
    for (int j = jb; j < jb + CANDS; ++j) {
        float d = d2_ref(cx, cy, cz, csq, sh[j]);
        d = (j == lc) ? INF : d;                 // exclude self
        float t0 = fminf(h0, d),  x1 = fmaxf(h0, d);  h0 = t0;
        float t1 = fminf(h1, x1), x2 = fmaxf(h1, x1); h1 = t1;
        float t2 = fminf(h2, x2), x3 = fmaxf(h2, x2); h2 = t2;
        h3 = fminf(h3, x3);
    }
    {
        float* P = pv + (c * PARTS + p) * 4;
        P[0] = h0; P[1] = h1; P[2] = h2; P[3] = h3;
    }
    __syncthreads();

    // ---- bound: max of the 16 kept values (= their 16th smallest) ----
    // each part keeps its 4 smallest non-self elements, all <= B
    // => >=16 non-self elements <= B => B >= true 16th smallest
    if (tid < CPB) {
        const float* P = pv + tid * PARTS * 4;
        float B = P[0];
#pragma unroll
        for (int e = 1; e < PARTS * 4; ++e) B = fmaxf(B, P[e]);
        bnd[tid] = B;
    }
    __syncthreads();

    // ---- pass 2: collect candidate indices with d2 <= B (self included) ----
    const float B = bnd[c];
#pragma unroll 4
    for (int j = jb; j < jb + CANDS; ++j) {
        float dd = d2_ref(cx, cy, cz, csq, sh[j]);
        if (dd <= B) {
            int s = atomicAdd(&cnt[c], 1);
            if (s < CAP) jbuf[c * CAP + s] = (unsigned short)j;
        }
    }
    __syncthreads();

    // ---- selection + filters + emit: one lane per center ----
    if (tid < CPB) {
        const int    lc2 = cb + tid;
        const float4 c0  = sh[lc2];
        const float  ax = c0.x, ay = c0.y, az = c0.z, asq = c0.w;

        unsigned long long hd[KNN];
#pragma unroll
        for (int t = 0; t < KNN; ++t) hd[t] = ~0ull;

        const int m = cnt[tid];
        if (m <= CAP) {
            for (int e = 0; e < m; ++e) {
                const int j = jbuf[tid * CAP + e];
                if (j == lc2) continue;          // skip self
                float d2 = d2_ref(ax, ay, az, asq, sh[j]);
                unsigned long long key =
                    ((unsigned long long)sortkey(d2) << 32) | (unsigned)j;
                if (key < hd[KNN - 1]) {
#pragma unroll
                    for (int t = 0; t < KNN; ++t) {
                        unsigned long long lo = key < hd[t] ? key : hd[t];
                        unsigned long long hi = key < hd[t] ? hd[t] : key;
                        hd[t] = lo; key = hi;
                    }
                }
            }
        } else {
            // overflow fallback: exact full scan (deterministic, ~never)
            for (int j = 0; j < NPG; ++j) {
                if (j == lc2) continue;
                float d2 = d2_ref(ax, ay, az, asq, sh[j]);
                unsigned long long key =
                    ((unsigned long long)sortkey(d2) << 32) | (unsigned)j;
                if (key < hd[KNN - 1]) {
#pragma unroll
                    for (int t = 0; t < KNN; ++t) {
                        unsigned long long lo = key < hd[t] ? key : hd[t];
                        unsigned long long hi = key < hd[t] ? hd[t] : key;
                        hd[t] = lo; key = hi;
                    }
                }
            }
        }

        const int ctr = gb + lc2;
#pragma unroll
        for (int k = 0; k < KNN; ++k) {
            float2 e = make_float2(-1.0f, -1.0f);
            if (hd[k] != ~0ull) {
                const int nl  = (int)(unsigned)(hd[k] & 0xFFFFFFFFull);
                const int nbr = gb + nl;
                const float4 v = sh[nl];
                // degenerate-edge filter, reference formula
                float dx = __fadd_rn(v.x, -ax);
                float dy = __fadd_rn(v.y, -ay);
                float dz = __fadd_rn(v.z, -az);
                float dn2 = __fadd_rn(__fadd_rn(__fmul_rn(dx, dx),
                                                __fmul_rn(dy, dy)),
                                      __fmul_rn(dz, dz));
                int  rd    = nbr > ctr ? (nbr - ctr) : (ctr - nbr);
                bool valid = (rd >= MIN_DISTR) && (sqrtf(dn2) >= 1e-10f);
                if (valid) e = make_float2((float)nbr, (float)ctr);
            }
            out[ctr * KNN + k] = e;
        }
    }
}

extern "C" void kernel_launch(void* const* d_in, const int* in_sizes, int n_in,
                              void* d_out, int out_size)
{
    const float* pos = (const float*)d_in[0];
    for (int i = 0; i < n_in; ++i)
        if (in_sizes[i] == BGRAPHS * NPG * 3) { pos = (const float*)d_in[i]; break; }
    float2* out = (float2*)d_out;

    cudaFuncSetAttribute(knn_kernel, cudaFuncAttributeMaxDynamicSharedMemorySize,
                         SMEM_TOTAL);
    dim3 grid(BGRAPHS * (NPG / CPB));   // 512 blocks: single wave (4/SM)
    dim3 block(THREADS);                // 256 threads
    knn_kernel<<<grid, block, SMEM_TOTAL>>>(pos, out);
}